// round 7
// baseline (speedup 1.0000x reference)
#include <cuda_runtime.h>
#include <math.h>

constexpr int NB = 64;
constexpr int NT = 12;
constexpr int ND = 256;
constexpr int NS = 512;
constexpr int NV = 512;
constexpr int GRAPH_STEPS = 3;

typedef unsigned long long ull;

// cross-kernel scratch (device globals; no allocation allowed)
__device__ float g_gsT[512 * 64];        // [k][b]
__device__ float g_hT[2 * 256 * 64];     // [br][col][b]  br0=feedback-hidden, br1=logits-hidden

__device__ __forceinline__ float gelu_f(float x) {
    return 0.5f * x * (1.0f + erff(x * 0.70710678118654752440f));
}
__device__ __forceinline__ float sigmoid_f(float x) {
    return 1.0f / (1.0f + expf(-x));
}

// ---- packed f32x2 helpers (FFMA2 path, sm_103a) ----
__device__ __forceinline__ ull pk2(float lo, float hi) {
    ull r; asm("mov.b64 %0, {%1, %2};" : "=l"(r) : "f"(lo), "f"(hi)); return r;
}
__device__ __forceinline__ ull fma2(ull a, ull b, ull c) {
    ull d; asm("fma.rn.f32x2 %0, %1, %2, %3;" : "=l"(d) : "l"(a), "l"(b), "l"(c)); return d;
}
__device__ __forceinline__ float2 upk(ull v) {
    float2 f; asm("mov.b64 {%0, %1}, %2;" : "=f"(f.x), "=f"(f.y) : "l"(v)); return f;
}

// ---------------------------------------------------------------------------
// Kernel 1: both gate MLPs + sparse graph readout, fused per batch.
// grid = 64 (= batch), 1024 threads.
//   gates: j = tid&255 (hidden col), kg = tid>>8 (K-chunk of 64).
//   Per k: 2 weight LDG + 3 LDS.128 (12 evidence rows, pair-packed) + 12 FFMA2.
//   K-partials combined by 3 sequential smem add rounds (no atomics).
//   Graph phase runs on the same block with gates in smem; writes gsT[k][b].
// ---------------------------------------------------------------------------
__global__ void __launch_bounds__(1024, 1)
k_gates_graph(const int* __restrict__ em,  const int* __restrict__ si,
              const int* __restrict__ sv,  const int* __restrict__ tsi,
              const int* __restrict__ tsv, const int* __restrict__ tvi,
              const int* __restrict__ tvv, const int* __restrict__ qi,
              const int* __restrict__ qv,
              const float* __restrict__ evidence,
              const float* __restrict__ symbol_emb,
              const float* __restrict__ value_emb,
              const float* __restrict__ Wmg1, const float* __restrict__ bmg1,
              const float* __restrict__ Wmg2, const float* __restrict__ bmg2,
              const float* __restrict__ Wsg1, const float* __restrict__ bsg1,
              const float* __restrict__ Wsg2, const float* __restrict__ bsg2)
{
    __shared__ __align__(16) float xT[ND * NT];        // 12 KB  xT[k][r]
    __shared__ __align__(16) float accbuf[24 * ND];    // 24 KB  partial rows; graph arrays overlay
    __shared__ float red[24][8];
    __shared__ float gate_s[24];                       // rows 0..11 mg, 12..23 sg
    __shared__ int   e_msrc[NT], e_mtgt[NT], e_ssrc[NT], e_stgt[NT];
    __shared__ float e_mval[NT], e_sval[NT];
    __shared__ int   scand[NT + 1], vcand[NT];
    __shared__ int   n_scand, n_vcand;

    const int b   = blockIdx.x;
    const int tid = threadIdx.x;
    const int j   = tid & 255;
    const int kg  = tid >> 8;

    // transpose-load evidence (3 rows per thread)
    #pragma unroll
    for (int r = kg * 3; r < kg * 3 + 3; r++)
        xT[j * NT + r] = evidence[(b * NT + r) * ND + j];

    // edge indices + validity masks (gates not needed yet)
    if (tid < NT) {
        const int t   = tid;
        const int mk  = em [b * NT + t];
        const int src = si [b * NT + t];
        const int svv = sv [b * NT + t];
        const int ts  = tsi[b * NT + t];
        const int tsx = tsv[b * NT + t];
        const int tv  = tvi[b * NT + t];
        const int tvx = tvv[b * NT + t];
        const int src_c = min(max(src, 0), NS - 1);
        const int ts_c  = min(max(ts,  0), NS - 1);
        const int tv_c  = min(max(tv,  0), NV - 1);
        const bool mm = ((mk == 0) || (mk == 1)) && (svv > 0) && (tvx > 0);
        const bool sm = (mk == 2) && (svv > 0) && (tsx > 0);
        e_msrc[t] = src_c; e_mtgt[t] = tv_c; e_mval[t] = mm ? 1.f : 0.f;
        e_ssrc[t] = src_c; e_stgt[t] = ts_c; e_sval[t] = sm ? 1.f : 0.f;
    }
    __syncthreads();

    // ---- gate K-loop: both gates, 64 k per thread ----
    ull am[6], as2[6];
    #pragma unroll
    for (int i = 0; i < 6; i++) { am[i] = 0ull; as2[i] = 0ull; }
    {
        const int k0 = kg * 64;
        #pragma unroll 4
        for (int kk = 0; kk < 64; kk++) {
            const int k = k0 + kk;
            const float wm = Wmg1[k * ND + j];
            const float ws = Wsg1[k * ND + j];
            const ull wpm = pk2(wm, wm);
            const ull wps = pk2(ws, ws);
            const ulonglong2* xp = (const ulonglong2*)(xT + k * NT);
            const ulonglong2 p0 = xp[0];
            const ulonglong2 p1 = xp[1];
            const ulonglong2 p2 = xp[2];
            am[0]  = fma2(p0.x, wpm, am[0]);   as2[0] = fma2(p0.x, wps, as2[0]);
            am[1]  = fma2(p0.y, wpm, am[1]);   as2[1] = fma2(p0.y, wps, as2[1]);
            am[2]  = fma2(p1.x, wpm, am[2]);   as2[2] = fma2(p1.x, wps, as2[2]);
            am[3]  = fma2(p1.y, wpm, am[3]);   as2[3] = fma2(p1.y, wps, as2[3]);
            am[4]  = fma2(p2.x, wpm, am[4]);   as2[4] = fma2(p2.x, wps, as2[4]);
            am[5]  = fma2(p2.y, wpm, am[5]);   as2[5] = fma2(p2.y, wps, as2[5]);
        }
    }

    // ---- combine K-partials: kg1 store, kg2 +=, kg3 += (no atomics) ----
    if (kg == 1) {
        #pragma unroll
        for (int i = 0; i < 6; i++) {
            const float2 fm = upk(am[i]), fs = upk(as2[i]);
            accbuf[(2 * i) * ND + j]          = fm.x;
            accbuf[(2 * i + 1) * ND + j]      = fm.y;
            accbuf[(12 + 2 * i) * ND + j]     = fs.x;
            accbuf[(12 + 2 * i + 1) * ND + j] = fs.y;
        }
    }
    __syncthreads();
    if (kg == 2) {
        #pragma unroll
        for (int i = 0; i < 6; i++) {
            const float2 fm = upk(am[i]), fs = upk(as2[i]);
            accbuf[(2 * i) * ND + j]          += fm.x;
            accbuf[(2 * i + 1) * ND + j]      += fm.y;
            accbuf[(12 + 2 * i) * ND + j]     += fs.x;
            accbuf[(12 + 2 * i + 1) * ND + j] += fs.y;
        }
    }
    __syncthreads();
    if (kg == 3) {
        #pragma unroll
        for (int i = 0; i < 6; i++) {
            const float2 fm = upk(am[i]), fs = upk(as2[i]);
            accbuf[(2 * i) * ND + j]          += fm.x;
            accbuf[(2 * i + 1) * ND + j]      += fm.y;
            accbuf[(12 + 2 * i) * ND + j]     += fs.x;
            accbuf[(12 + 2 * i + 1) * ND + j] += fs.y;
        }
    }
    __syncthreads();

    // ---- gelu + W2 weighting + row reduction (kg0 holds its own partial) ----
    if (kg == 0) {
        const float b1m = bmg1[j], w2m = Wmg2[j];
        const float b1s = bsg1[j], w2s = Wsg2[j];
        const int lane = j & 31, warp = j >> 5;
        #pragma unroll
        for (int i = 0; i < 6; i++) {
            const float2 fm = upk(am[i]), fs = upk(as2[i]);
            #pragma unroll
            for (int hh = 0; hh < 2; hh++) {
                const int r = 2 * i + hh;
                float vm = gelu_f((hh ? fm.y : fm.x) + accbuf[r * ND + j] + b1m) * w2m;
                float vs = gelu_f((hh ? fs.y : fs.x) + accbuf[(12 + r) * ND + j] + b1s) * w2s;
                #pragma unroll
                for (int off = 16; off > 0; off >>= 1) {
                    vm += __shfl_xor_sync(0xffffffffu, vm, off);
                    vs += __shfl_xor_sync(0xffffffffu, vs, off);
                }
                if (lane == 0) { red[r][warp] = vm; red[12 + r][warp] = vs; }
            }
        }
    }
    __syncthreads();

    // ---- final gate scalars + init graph arrays (accbuf now dead -> overlay) ----
    float* walk  = accbuf;
    float* nwalk = accbuf + 512;
    float* wsum  = accbuf + 1024;
    float* vw    = accbuf + 1536;

    if (tid < 24) {
        float s = 0.f;
        #pragma unroll
        for (int w = 0; w < 8; w++) s += red[tid][w];
        const float b2 = (tid < 12) ? bmg2[0] : bsg2[0];
        gate_s[tid] = sigmoid_f(s + b2);
    }
    if (tid < NS) { walk[tid] = 0.f; wsum[tid] = 0.f; vw[tid] = 0.f; }
    __syncthreads();

    if (tid == 0) {
        const int q = min(max(qi[b], 0), NS - 1);
        if (qv[b] > 0) walk[q] = 1.0f;
        int n = 0;
        scand[n++] = q;
        for (int t = 0; t < NT; t++) {
            const int c = e_stgt[t];
            bool dup = false;
            for (int k = 0; k < n; k++) dup |= (scand[k] == c);
            if (!dup) scand[n++] = c;
        }
        n_scand = n;
        int m = 0;
        for (int t = 0; t < NT; t++) {
            const int c = e_mtgt[t];
            bool dup = false;
            for (int k = 0; k < m; k++) dup |= (vcand[k] == c);
            if (!dup) vcand[m++] = c;
        }
        n_vcand = m;
    }
    if (tid < NT) {
        e_mval[tid] *= gate_s[tid];
        e_sval[tid] *= gate_s[12 + tid];
    }
    __syncthreads();

    // ---- walk evolution, warp 0 only (support <= 13) ----
    if (tid < 32) {
        const int nsc = n_scand;
        for (int iter = 0; iter <= GRAPH_STEPS; iter++) {
            if (tid < nsc) wsum[scand[tid]] += walk[scand[tid]];
            if (tid < NT) {
                const float c = walk[e_msrc[tid]] * e_mval[tid];
                if (c != 0.f) atomicAdd(&vw[e_mtgt[tid]], c);
            }
            __syncwarp();
            if (iter < GRAPH_STEPS) {
                if (tid < nsc) nwalk[scand[tid]] = 0.f;
                __syncwarp();
                if (tid < NT) {
                    const float c = walk[e_ssrc[tid]] * e_sval[tid];
                    if (c != 0.f) atomicAdd(&nwalk[e_stgt[tid]], c);
                }
                __syncwarp();
                if (tid < nsc) walk[scand[tid]] = nwalk[scand[tid]];
                __syncwarp();
            }
        }
    }
    __syncthreads();

    // ---- sparse gather -> gsT[k][b] ----
    if (tid < 512) {
        float rres;
        if (tid < 256) {
            float accs = 0.f;
            const int nsc = n_scand;
            for (int c = 0; c < nsc; c++) {
                const int s = scand[c];
                accs = fmaf(wsum[s], symbol_emb[s * ND + tid], accs);
            }
            rres = accs;
        } else {
            const int d = tid - 256;
            float vpart = 0.f;
            const int nvc = n_vcand;
            for (int c = 0; c < nvc; c++) {
                const int v = vcand[c];
                vpart = fmaf(vw[v], value_emb[v * ND + d], vpart);
            }
            rres = vpart;
        }
        g_gsT[tid * 64 + b] = rres;
    }
}

// ---------------------------------------------------------------------------
// Kernel 2: layer-1 batch-shared GEMM + gelu.
// grid = 128 = br(2) x col-tile(64, 4 cols each).  1024 threads:
//   ks = tid>>7 (K-chunk 64), c = (tid&127)>>5, bp = tid&31 (batch pair).
// Weight load is warp-uniform; activation load coalesced over batch.
// ---------------------------------------------------------------------------
__global__ void __launch_bounds__(1024, 1)
k_l1(const float* __restrict__ Wf1, const float* __restrict__ bf1,
     const float* __restrict__ Wo1, const float* __restrict__ bo1)
{
    __shared__ ull part[1024];
    const int bid = blockIdx.x;
    const int br  = bid >> 6;
    const int t   = bid & 63;
    const int tid = threadIdx.x;

    const float* __restrict__ W1 = br ? Wo1 : Wf1;
    const float* __restrict__ B1 = br ? bo1 : bf1;

    const int ks = tid >> 7;
    const int rem = tid & 127;
    const int c  = rem >> 5;
    const int bp = rem & 31;
    const int gcol = t * 4 + c;

    ull acc = 0ull;
    const int k0 = ks * 64;
    #pragma unroll 8
    for (int kk = 0; kk < 64; kk++) {
        const int k = k0 + kk;
        const float wv = W1[k * ND + gcol];
        const ull av = *(const ull*)(g_gsT + k * 64 + 2 * bp);
        acc = fma2(av, pk2(wv, wv), acc);
    }
    part[tid] = acc;
    __syncthreads();

    if (tid < 128) {
        float s0 = 0.f, s1 = 0.f;
        #pragma unroll
        for (int k2 = 0; k2 < 8; k2++) {
            const float2 f = upk(part[k2 * 128 + tid]);
            s0 += f.x; s1 += f.y;
        }
        const int c2 = tid >> 5, bp2 = tid & 31;
        const int col = t * 4 + c2;
        const float bb = B1[col];
        float2 hv;
        hv.x = gelu_f(s0 + bb);
        hv.y = gelu_f(s1 + bb);
        *(float2*)(g_hT + (br * 256 + col) * 64 + 2 * bp2) = hv;
    }
}

// ---------------------------------------------------------------------------
// Kernel 3: layer-2 batch-shared GEMMs + bias -> out.
// grid = 96: blocks 0..63 logits (8 cols each), 64..95 feedback (8 cols each).
//   ks = tid>>8 (K-chunk 64), c = (tid&255)>>5, bp = tid&31.
// ---------------------------------------------------------------------------
__global__ void __launch_bounds__(1024, 1)
k_l2(const float* __restrict__ Wf2, const float* __restrict__ bf2,
     const float* __restrict__ Wo2, const float* __restrict__ bo2,
     float* __restrict__ out)
{
    __shared__ ull part[1024];
    const int bid = blockIdx.x;
    const int tid = threadIdx.x;
    const bool lg = (bid < 64);
    const int t = lg ? bid : (bid - 64);

    const int ks = tid >> 8;
    const int rem = tid & 255;
    const int c  = rem >> 5;
    const int bp = rem & 31;
    const int gcol = t * 8 + c;

    const float* __restrict__ W = lg ? Wo2 : Wf2;
    const int wstride = lg ? NV : ND;
    const int hbase   = lg ? 256 : 0;

    ull acc = 0ull;
    const int k0 = ks * 64;
    #pragma unroll 8
    for (int kk = 0; kk < 64; kk++) {
        const int k = k0 + kk;
        const float wv = W[k * wstride + gcol];
        const ull av = *(const ull*)(g_hT + (hbase + k) * 64 + 2 * bp);
        acc = fma2(av, pk2(wv, wv), acc);
    }
    part[tid] = acc;
    __syncthreads();

    if (tid < 256) {
        float s0 = 0.f, s1 = 0.f;
        #pragma unroll
        for (int k2 = 0; k2 < 4; k2++) {
            const float2 f = upk(part[k2 * 256 + tid]);
            s0 += f.x; s1 += f.y;
        }
        const int c2 = tid >> 5, bp2 = tid & 31;
        const int col = t * 8 + c2;
        if (lg) {
            const float bb = bo2[col];
            out[(2 * bp2) * NV + col]     = s0 + bb;
            out[(2 * bp2 + 1) * NV + col] = s1 + bb;
        } else {
            const float bb = bf2[col];
            out[NB * NV + (2 * bp2) * ND + col]     = s0 + bb;
            out[NB * NV + (2 * bp2 + 1) * ND + col] = s1 + bb;
        }
    }
}

// ---------------------------------------------------------------------------
extern "C" void kernel_launch(void* const* d_in, const int* in_sizes, int n_in,
                              void* d_out, int out_size)
{
    const int*   event_marker       = (const int*)  d_in[0];
    const int*   source_idx         = (const int*)  d_in[1];
    const int*   source_valid       = (const int*)  d_in[2];
    const int*   target_symbol_idx  = (const int*)  d_in[3];
    const int*   target_symbol_vld  = (const int*)  d_in[4];
    const int*   target_value_idx   = (const int*)  d_in[5];
    const int*   target_value_vld   = (const int*)  d_in[6];
    const int*   query_idx          = (const int*)  d_in[7];
    const int*   query_valid        = (const int*)  d_in[8];
    const float* evidence           = (const float*)d_in[9];
    const float* symbol_emb         = (const float*)d_in[10];
    const float* value_emb          = (const float*)d_in[11];
    const float* Wmg1 = (const float*)d_in[12];
    const float* bmg1 = (const float*)d_in[13];
    const float* Wmg2 = (const float*)d_in[14];
    const float* bmg2 = (const float*)d_in[15];
    const float* Wsg1 = (const float*)d_in[16];
    const float* bsg1 = (const float*)d_in[17];
    const float* Wsg2 = (const float*)d_in[18];
    const float* bsg2 = (const float*)d_in[19];
    const float* Wf1  = (const float*)d_in[20];
    const float* bf1  = (const float*)d_in[21];
    const float* Wf2  = (const float*)d_in[22];
    const float* bf2  = (const float*)d_in[23];
    const float* Wo1  = (const float*)d_in[24];
    const float* bo1  = (const float*)d_in[25];
    const float* Wo2  = (const float*)d_in[26];
    const float* bo2  = (const float*)d_in[27];

    float* out = (float*)d_out;

    k_gates_graph<<<NB, 1024>>>(event_marker, source_idx, source_valid,
                                target_symbol_idx, target_symbol_vld,
                                target_value_idx, target_value_vld,
                                query_idx, query_valid,
                                evidence, symbol_emb, value_emb,
                                Wmg1, bmg1, Wmg2, bmg2,
                                Wsg1, bsg1, Wsg2, bsg2);
    k_l1<<<128, 1024>>>(Wf1, bf1, Wo1, bo1);
    k_l2<<<96, 1024>>>(Wf2, bf2, Wo2, bo2, out);
}